// round 15
// baseline (speedup 1.0000x reference)
#include <cuda_runtime.h>
#include <math.h>

// ESN recurrence, GB300 sm_103a.
// R15 = R14 sync (release-store flags + acquire-v4 poll, best: 3984us) with a
// restructured compute body:
//  - U folded into the main accumulators (computed during the wait from
//    register-resident W_in slices; no s_in/s_u, no U shuffle tree)
//  - warp-owns-2-rows: lane reads xs4[c*32+lane] (conflict-free LDS.128),
//    6-shuffle select-merge reduction, lanes 0/16 erf+store directly
//    (no s_part round-trip, no 16-thread serial finalize)
//  - 3 syncthreads per step instead of 5
//
// Shapes: input (2048,128) f32, W_in (2048,128) f32, W_res (2048,2048) f32,
// out (2048,2048) f32.  out[t] = erf(U[t] + W_res @ out[t-1]) / sqrt(2048).

#define T_STEPS 2048
#define N_RES   2048
#define D_IN    128
#define G_BLOCKS 128
#define ROWS_PER_BLOCK 16
#define THREADS 256

__device__ unsigned int g_flags[G_BLOCKS];

__global__ void esn_reset_kernel() { g_flags[threadIdx.x] = 0u; }

__device__ __forceinline__ void st_release_gpu(unsigned int* p, unsigned v) {
    asm volatile("st.release.gpu.global.u32 [%0], %1;" :: "l"(p), "r"(v) : "memory");
}
__device__ __forceinline__ uint4 ld_acquire_gpu_v4(const unsigned int* p) {
    uint4 v;
    asm volatile("ld.acquire.gpu.global.v4.u32 {%0,%1,%2,%3}, [%4];"
                 : "=r"(v.x), "=r"(v.y), "=r"(v.z), "=r"(v.w) : "l"(p) : "memory");
    return v;
}

__global__ void __launch_bounds__(THREADS, 1)
esn_persistent_kernel(const float* __restrict__ input,
                      const float* __restrict__ Win,
                      const float* __restrict__ Wres,
                      float* __restrict__ out)
{
    __shared__ float4 xs4[N_RES / 4];    // 8 KB: x_{t-1} staged once per block

    const int tid  = threadIdx.x;
    const int warp = tid >> 5;           // 0..7; warp owns rows {2w, 2w+1}
    const int lane = tid & 31;
    const int row0 = blockIdx.x * ROWS_PER_BLOCK;
    const int r0   = row0 + 2 * warp;    // this warp's first row

    // ---- one-time: W_in slices -> registers (lane's 4-elem input slice) ----
    const float4 win0 = *reinterpret_cast<const float4*>(Win + (size_t)(r0 + 0) * D_IN + lane * 4);
    const float4 win1 = *reinterpret_cast<const float4*>(Win + (size_t)(r0 + 1) * D_IN + lane * 4);

    // ---- one-time: W_res -> registers. Lane's k-set matches the smem read
    //      xs4[c*32 + lane]  =>  k = c*128 + lane*4 + (0..3), c = 0..15. ----
    float4 w0[16], w1[16];
    #pragma unroll
    for (int c = 0; c < 16; c++) {
        w0[c] = *reinterpret_cast<const float4*>(Wres + (size_t)(r0 + 0) * N_RES + c * 128 + lane * 4);
        w1[c] = *reinterpret_cast<const float4*>(Wres + (size_t)(r0 + 1) * N_RES + c * 128 + lane * 4);
    }

    const float inv_sqrt_n = 0.022097086912079608f;  // 1/sqrt(2048)

    for (int t = 0; t < T_STEPS; t++) {
        // ---- U part first (x-independent; overlaps peers finishing t-1):
        //      acc starts as this lane's share of U[t][row] ----
        const float4 in4 = __ldg(reinterpret_cast<const float4*>(input + (size_t)t * D_IN) + lane);
        float acc0 = in4.x * win0.x, acc1 = in4.x * win1.x;
        acc0 = fmaf(in4.y, win0.y, acc0);  acc1 = fmaf(in4.y, win1.y, acc1);
        acc0 = fmaf(in4.z, win0.z, acc0);  acc1 = fmaf(in4.z, win1.z, acc1);
        acc0 = fmaf(in4.w, win0.w, acc0);  acc1 = fmaf(in4.w, win1.w, acc1);

        if (t > 0) {
            // ---- grid wait: warp 0 polls 128 flags, 1 acquire-v4 per lane ----
            if (warp == 0) {
                const unsigned tgt = (unsigned)t;
                const unsigned int* f = g_flags + lane * 4;
                while (true) {
                    const uint4 v = ld_acquire_gpu_v4(f);
                    const bool done = min(min(v.x, v.y), min(v.z, v.w)) >= tgt;
                    if (__ballot_sync(0xffffffffu, done) == 0xffffffffu) break;
                }
            }
            __syncthreads();   // poll done + previous-step xs4 reads done (WAR)

            // ---- stage x_{t-1} = out[t-1][:] through L2 into smem ----
            const float4* xprev = reinterpret_cast<const float4*>(out + (size_t)(t - 1) * N_RES);
            xs4[tid]           = __ldcg(xprev + tid);
            xs4[tid + THREADS] = __ldcg(xprev + tid + THREADS);
            __syncthreads();

            // ---- main dot: 16 conflict-free LDS.128 + 128 FFMA per lane ----
            #pragma unroll
            for (int c = 0; c < 16; c++) {
                const float4 xv = xs4[c * 32 + lane];
                acc0 = fmaf(w0[c].x, xv.x, acc0);
                acc0 = fmaf(w0[c].y, xv.y, acc0);
                acc0 = fmaf(w0[c].z, xv.z, acc0);
                acc0 = fmaf(w0[c].w, xv.w, acc0);
                acc1 = fmaf(w1[c].x, xv.x, acc1);
                acc1 = fmaf(w1[c].y, xv.y, acc1);
                acc1 = fmaf(w1[c].z, xv.z, acc1);
                acc1 = fmaf(w1[c].w, xv.w, acc1);
            }
        }

        // ---- 6-shuffle select-merge reduction (U included):
        //      lane 0 -> row r0, lane 16 -> row r0+1 ----
        acc0 += __shfl_xor_sync(0xffffffffu, acc0, 16);
        acc1 += __shfl_xor_sync(0xffffffffu, acc1, 16);
        float e = (lane & 16) ? acc1 : acc0;
        e += __shfl_xor_sync(0xffffffffu, e, 8);
        e += __shfl_xor_sync(0xffffffffu, e, 4);
        e += __shfl_xor_sync(0xffffffffu, e, 2);
        e += __shfl_xor_sync(0xffffffffu, e, 1);

        if ((lane & 15) == 0) {
            const int row = r0 + (lane >> 4);
            out[(size_t)t * N_RES + row] = erff(e) * inv_sqrt_n;
        }
        __syncthreads();   // all rows of this block stored

        // ---- publish: release-store own flag ----
        if (tid == 0)
            st_release_gpu(&g_flags[blockIdx.x], (unsigned)(t + 1));
    }
}

extern "C" void kernel_launch(void* const* d_in, const int* in_sizes, int n_in,
                              void* d_out, int out_size)
{
    const float* input = (const float*)d_in[0];   // (2048, 128)
    const float* Win   = (const float*)d_in[1];   // (2048, 128)
    const float* Wres  = (const float*)d_in[2];   // (2048, 2048)
    float* out = (float*)d_out;                   // (2048, 2048)

    esn_reset_kernel<<<1, G_BLOCKS>>>();
    esn_persistent_kernel<<<G_BLOCKS, THREADS>>>(input, Win, Wres, out);
}

// round 17
// speedup vs baseline: 2.2294x; 2.2294x over previous
#include <cuda_runtime.h>
#include <math.h>

// ESN recurrence, GB300 sm_103a.
// R16 = R14 compute body (4 rowgroups x 64 kc, 4 acc chains, dedicated
// finalize; best: 3984us) with the handoff restructured:
//  - per-WARP gate: warp w waits only on the 64 producers of its x half
//    (one ld.acquire.gpu.v2 per lane + ballot), not all 128
//  - x read directly with coalesced LDG.128 (lane q-loop: x4[h*256+q*32+lane]),
//    no smem staging, no post-poll syncthreads pair
//  - W registers gathered at init to match the new per-lane k-assignment
// Publish identical to R14: bar + tid0 st.release.gpu to own flag.
//
// Shapes: input (2048,128) f32, W_in (2048,128) f32, W_res (2048,2048) f32,
// out (2048,2048) f32.  out[t] = erf(U[t] + W_res @ out[t-1]) / sqrt(2048).

#define T_STEPS 2048
#define N_RES   2048
#define D_IN    128
#define G_BLOCKS 128
#define ROWS_PER_BLOCK 16
#define THREADS 256

__device__ unsigned int g_flags[G_BLOCKS];

__global__ void esn_reset_kernel() { g_flags[threadIdx.x] = 0u; }

__device__ __forceinline__ void st_release_gpu(unsigned int* p, unsigned v) {
    asm volatile("st.release.gpu.global.u32 [%0], %1;" :: "l"(p), "r"(v) : "memory");
}
__device__ __forceinline__ uint2 ld_acquire_gpu_v2(const unsigned int* p) {
    uint2 v;
    asm volatile("ld.acquire.gpu.global.v2.u32 {%0,%1}, [%2];"
                 : "=r"(v.x), "=r"(v.y) : "l"(p) : "memory");
    return v;
}

__global__ void __launch_bounds__(THREADS, 1)
esn_persistent_kernel(const float* __restrict__ input,
                      const float* __restrict__ Win,
                      const float* __restrict__ Wres,
                      float* __restrict__ out)
{
    __shared__ float s_win[ROWS_PER_BLOCK * D_IN];   // 8 KB: W_in slice
    __shared__ float s_in[D_IN];                     // input row t
    __shared__ float s_part[32];                     // 8 warps * 4 rows
    __shared__ float s_u[ROWS_PER_BLOCK];            // U[t][rows]

    const int tid  = threadIdx.x;
    const int warp = tid >> 5;
    const int lane = tid & 31;
    const int rg   = warp >> 1;    // 0..3: rowgroup (4 rows each)
    const int h    = warp & 1;     // x half: k in [h*1024, h*1024+1024)
    const int row0 = blockIdx.x * ROWS_PER_BLOCK;

    // ---- one-time: W_in slice to SMEM ----
    for (int i = tid; i < ROWS_PER_BLOCK * D_IN; i += THREADS)
        s_win[i] = Win[row0 * D_IN + i];

    // ---- one-time: W_res tile into registers, gathered to match the
    //      coalesced x read: lane's k-set = { h*1024 + q*128 + lane*4 + 0..3 }.
    float4 w4[4][8];
    #pragma unroll
    for (int rr = 0; rr < 4; rr++) {
        const float* wrow = Wres + (size_t)(row0 + rg * 4 + rr) * N_RES + h * 1024 + lane * 4;
        #pragma unroll
        for (int q = 0; q < 8; q++)
            w4[rr][q] = *reinterpret_cast<const float4*>(wrow + q * 128);
    }
    __syncthreads();

    const float inv_sqrt_n = 0.022097086912079608f;  // 1/sqrt(2048)

    for (int t = 0; t < T_STEPS; t++) {
        // ---- stage input row t (x-independent) ----
        if (tid < D_IN / 4) {
            float4 v = __ldcg(reinterpret_cast<const float4*>(input + (size_t)t * D_IN) + tid);
            reinterpret_cast<float4*>(s_in)[tid] = v;
        }
        __syncthreads();

        // ---- U[t][row] = dot(input[t], W_in[row]); 16 threads/row ----
        {
            const int row = tid >> 4;
            const int seg = tid & 15;
            float us = 0.f;
            #pragma unroll
            for (int j = 0; j < 8; j++) {
                const int k = seg * 8 + j;
                us += s_in[k] * s_win[row * D_IN + k];
            }
            #pragma unroll
            for (int off = 8; off; off >>= 1)
                us += __shfl_down_sync(0xffffffffu, us, off, 16);
            if (seg == 0) s_u[row] = us;
        }

        // ---- main dot (per-warp gate + direct coalesced x loads) ----
        float acc0 = 0.f, acc1 = 0.f, acc2 = 0.f, acc3 = 0.f;
        if (t > 0) {
            // wait only for this warp's 64 producers (its x half)
            {
                const unsigned tgt = (unsigned)t;
                const unsigned int* f = g_flags + h * 64 + lane * 2;
                while (true) {
                    const uint2 v = ld_acquire_gpu_v2(f);
                    const bool done = min(v.x, v.y) >= tgt;
                    if (__ballot_sync(0xffffffffu, done) == 0xffffffffu) break;
                }
            }

            // coalesced direct read of this warp's x half (write-once lines,
            // L1-cacheable; redundant rowgroup reads MSHR-merge)
            const float4* x4 = reinterpret_cast<const float4*>(out + (size_t)(t - 1) * N_RES)
                               + h * 256 + lane;
            float4 xb[8];
            #pragma unroll
            for (int q = 0; q < 8; q++)
                xb[q] = x4[q * 32];

            #pragma unroll
            for (int q = 0; q < 8; q++) {
                const float4 xv = xb[q];
                acc0 = fmaf(w4[0][q].x, xv.x, acc0);
                acc0 = fmaf(w4[0][q].y, xv.y, acc0);
                acc0 = fmaf(w4[0][q].z, xv.z, acc0);
                acc0 = fmaf(w4[0][q].w, xv.w, acc0);
                acc1 = fmaf(w4[1][q].x, xv.x, acc1);
                acc1 = fmaf(w4[1][q].y, xv.y, acc1);
                acc1 = fmaf(w4[1][q].z, xv.z, acc1);
                acc1 = fmaf(w4[1][q].w, xv.w, acc1);
                acc2 = fmaf(w4[2][q].x, xv.x, acc2);
                acc2 = fmaf(w4[2][q].y, xv.y, acc2);
                acc2 = fmaf(w4[2][q].z, xv.z, acc2);
                acc2 = fmaf(w4[2][q].w, xv.w, acc2);
                acc3 = fmaf(w4[3][q].x, xv.x, acc3);
                acc3 = fmaf(w4[3][q].y, xv.y, acc3);
                acc3 = fmaf(w4[3][q].z, xv.z, acc3);
                acc3 = fmaf(w4[3][q].w, xv.w, acc3);
            }
        }

        // ---- reduce across 32 lanes (R14 verbatim) ----
        #pragma unroll
        for (int off = 16; off; off >>= 1) {
            acc0 += __shfl_xor_sync(0xffffffffu, acc0, off);
            acc1 += __shfl_xor_sync(0xffffffffu, acc1, off);
            acc2 += __shfl_xor_sync(0xffffffffu, acc2, off);
            acc3 += __shfl_xor_sync(0xffffffffu, acc3, off);
        }
        if (lane == 0) {
            s_part[warp * 4 + 0] = acc0;
            s_part[warp * 4 + 1] = acc1;
            s_part[warp * 4 + 2] = acc2;
            s_part[warp * 4 + 3] = acc3;
        }
        __syncthreads();

        // ---- finalize 16 rows (R14 verbatim) ----
        if (tid < ROWS_PER_BLOCK) {
            const int rg2 = tid >> 2;
            const int rr  = tid & 3;
            const float sum = s_part[(rg2 * 2 + 0) * 4 + rr] +
                              s_part[(rg2 * 2 + 1) * 4 + rr];
            const float pre = s_u[tid] + sum;
            out[(size_t)t * N_RES + row0 + tid] = erff(pre) * inv_sqrt_n;
        }
        __syncthreads();

        // ---- publish: release-store own flag ----
        if (tid == 0)
            st_release_gpu(&g_flags[blockIdx.x], (unsigned)(t + 1));
    }
}

extern "C" void kernel_launch(void* const* d_in, const int* in_sizes, int n_in,
                              void* d_out, int out_size)
{
    const float* input = (const float*)d_in[0];   // (2048, 128)
    const float* Win   = (const float*)d_in[1];   // (2048, 128)
    const float* Wres  = (const float*)d_in[2];   // (2048, 2048)
    float* out = (float*)d_out;                   // (2048, 2048)

    esn_reset_kernel<<<1, G_BLOCKS>>>();
    esn_persistent_kernel<<<G_BLOCKS, THREADS>>>(input, Win, Wres, out);
}